// round 15
// baseline (speedup 1.0000x reference)
#include <cuda_runtime.h>

#define NT      250000
#define NNODES  20000
#define EMB     64
#define NC      16
#define NRP     (NNODES*8)
#define NBLK    148

// ---------------- scratch (statically zero-initialized at module load) ------
__device__ __align__(16) float g_l1[NT*8];       // raw l1
__device__ __align__(16) float g_l2[NT*8];       // softmaxed l2
__device__ float g_colsum[NRP];
__device__ float g_rowsum[NRP];
__device__ __align__(16) float g_invC[NRP];      // [o][p] = 1/colsum[o*p]
__device__ __align__(16) float g_invR[NRP];      // [s][p] = 1/max(rowsum[s*p],1e-6)
__device__ __align__(16) float g_h[NNODES*EMB];
__device__ __align__(16) float g_h2[NNODES*128]; // H2[o][r*16+c] = h[o] @ W2[r]
__device__ int   g_cnt_s[NNODES];
__device__ int   g_cnt_o[NNODES];
__device__ int   g_off_s[NNODES+1];
__device__ int   g_off_o[NNODES+1];
__device__ int   g_cur_s[NNODES];
__device__ int   g_cur_o[NNODES];
__device__ int   g_perm_s[NT];
__device__ int   g_perm_o[NT];
__device__ float g_out0[64*16];                  // striped partials for p=0 logits
__device__ int   g_flag;                         // scan-done flag
__device__ int   g_done1;                        // scatter-done counter
__device__ int   g_done2;                        // sums-done counter

__device__ __forceinline__ int   LDCG_I(const int* p)   { return __ldcg(p); }
__device__ __forceinline__ float LDCG_F(const float* p) { return __ldcg(p); }

// ---------------- K1: GEMMs + softmax (NO float scatter atomics) -------------
__global__ __launch_bounds__(256) void k1_l1l2(
    const float* __restrict__ rm,
    const float* __restrict__ Wl1, const float* __restrict__ bl1,
    const float* __restrict__ Wl2, const float* __restrict__ bl2,
    const int* __restrict__ hrow, const int* __restrict__ vcol)
{
    __shared__ float4 sW14[128], sW24[128];
    __shared__ float sb1[8], sb2[8];
    int tid = threadIdx.x;
    if (tid < 128) { sW14[tid] = ((const float4*)Wl1)[tid]; sW24[tid] = ((const float4*)Wl2)[tid]; }
    if (tid < 8) { sb1[tid] = bl1[tid]; sb2[tid] = bl2[tid]; }
    __syncthreads();

    int row = blockIdx.x * 256 + tid;
    const float4* rm4 = (const float4*)rm;

    float a1[8], a2[8];
#pragma unroll
    for (int p = 0; p < 8; p++) { a1[p] = sb1[p]; a2[p] = sb2[p]; }

    if (row < NT) {
        for (int k4 = 0; k4 < 16; k4++) {
            float4 x = rm4[(size_t)row * 16 + k4];
#pragma unroll
            for (int j = 0; j < 4; j++) {
                int k = k4 * 4 + j;
                float4 w1lo = sW14[k*2], w1hi = sW14[k*2+1];
                float4 w2lo = sW24[k*2], w2hi = sW24[k*2+1];
                float xv = (j == 0) ? x.x : (j == 1) ? x.y : (j == 2) ? x.z : x.w;
                a1[0] = fmaf(xv, w1lo.x, a1[0]);
                a1[1] = fmaf(xv, w1lo.y, a1[1]);
                a1[2] = fmaf(xv, w1lo.z, a1[2]);
                a1[3] = fmaf(xv, w1lo.w, a1[3]);
                a1[4] = fmaf(xv, w1hi.x, a1[4]);
                a1[5] = fmaf(xv, w1hi.y, a1[5]);
                a1[6] = fmaf(xv, w1hi.z, a1[6]);
                a1[7] = fmaf(xv, w1hi.w, a1[7]);
                a2[0] = fmaf(xv, w2lo.x, a2[0]);
                a2[1] = fmaf(xv, w2lo.y, a2[1]);
                a2[2] = fmaf(xv, w2lo.z, a2[2]);
                a2[3] = fmaf(xv, w2lo.w, a2[3]);
                a2[4] = fmaf(xv, w2hi.x, a2[4]);
                a2[5] = fmaf(xv, w2hi.y, a2[5]);
                a2[6] = fmaf(xv, w2hi.z, a2[6]);
                a2[7] = fmaf(xv, w2hi.w, a2[7]);
            }
        }
    }

    float p0l1 = 0.f, p0l2 = 0.f;
    if (row < NT) {
        float m = a2[0];
#pragma unroll
        for (int p = 1; p < 8; p++) m = fmaxf(m, a2[p]);
        float e[8], ssum = 0.f;
#pragma unroll
        for (int p = 0; p < 8; p++) { e[p] = __expf(a2[p] - m); ssum += e[p]; }
        float inv = 1.f / ssum;
#pragma unroll
        for (int p = 0; p < 8; p++) e[p] *= inv;

        float4* d1 = (float4*)(g_l1 + (size_t)row * 8);
        float4* d2 = (float4*)(g_l2 + (size_t)row * 8);
        d1[0] = make_float4(a1[0], a1[1], a1[2], a1[3]);
        d1[1] = make_float4(a1[4], a1[5], a1[6], a1[7]);
        d2[0] = make_float4(e[0], e[1], e[2], e[3]);
        d2[1] = make_float4(e[4], e[5], e[6], e[7]);

        int o = vcol[row], s = hrow[row];
        p0l1 = a1[0];
        p0l2 = e[0];
        atomicAdd(&g_cnt_s[s], 1);
        atomicAdd(&g_cnt_o[o], 1);
    }

    int lane = tid & 31, wid = tid >> 5;
#pragma unroll
    for (int d = 16; d > 0; d >>= 1) {
        p0l1 += __shfl_down_sync(0xffffffffu, p0l1, d);
        p0l2 += __shfl_down_sync(0xffffffffu, p0l2, d);
    }
    __shared__ float red1[8], red2[8];
    if (lane == 0) { red1[wid] = p0l1; red2[wid] = p0l2; }
    __syncthreads();
    if (tid == 0) {
        float s1 = 0.f, s2 = 0.f;
#pragma unroll
        for (int w = 0; w < 8; w++) { s1 += red1[w]; s2 += red2[w]; }
        atomicAdd(&g_colsum[0], s1);
        atomicAdd(&g_rowsum[0], s2);
    }
}

// ---------------- helper: one-block exclusive scan (1024 threads) -----------
__device__ __forceinline__ void scan_block(const int* __restrict__ cnt,
                                           int* __restrict__ off,
                                           int* __restrict__ cur,
                                           int* __restrict__ wsum) {
    int tid = threadIdx.x;
    const int CH = 20;
    int base = tid * CH;
    int loc[CH]; int sum = 0;
#pragma unroll
    for (int j = 0; j < CH; j++) {
        int idx = base + j;
        int v = (idx < NNODES) ? cnt[idx] : 0;
        loc[j] = v; sum += v;
    }
    int lane = tid & 31, wid = tid >> 5;
    int x = sum;
#pragma unroll
    for (int d = 1; d < 32; d <<= 1) {
        int y = __shfl_up_sync(0xffffffffu, x, d);
        if (lane >= d) x += y;
    }
    if (lane == 31) wsum[wid] = x;
    __syncthreads();
    if (wid == 0) {
        int w = wsum[lane];
#pragma unroll
        for (int d = 1; d < 32; d <<= 1) {
            int y = __shfl_up_sync(0xffffffffu, w, d);
            if (lane >= d) w += y;
        }
        wsum[lane] = w;
    }
    __syncthreads();
    int run = x - sum + (wid ? wsum[wid - 1] : 0);
#pragma unroll
    for (int j = 0; j < CH; j++) {
        int idx = base + j;
        if (idx < NNODES) { off[idx] = run; cur[idx] = run; run += loc[j]; }
    }
    if (tid == 1023) off[NNODES] = wsum[31];
    __syncthreads();
}

// ---------------- K34: scan both + scatter both + gather sums + inv ----------
// 148 blocks x 1024 (all resident; spin barriers safe).
__global__ __launch_bounds__(1024) void k34_scan_scatter(
    const int* __restrict__ hrow, const int* __restrict__ vcol,
    float* __restrict__ out, const float* __restrict__ bias2)
{
    int tid = threadIdx.x, bid = blockIdx.x;
    __shared__ int wsum[32];

    // Phase A: block 0 scans both histograms
    if (bid == 0) {
        scan_block(g_cnt_s, g_off_s, g_cur_s, wsum);
        scan_block(g_cnt_o, g_off_o, g_cur_o, wsum);
        __threadfence();
        if (tid == 0) atomicExch(&g_flag, 1);
    } else {
        if (tid == 0) {
            while (atomicAdd(&g_flag, 0) == 0) __nanosleep(128);
        }
        __syncthreads();
    }

    int i = bid * 1024 + tid;
    const int stride = NBLK * 1024;

    // Phase B: scatter both CSRs
    for (int t = i; t < NT; t += stride) {
        int s = hrow[t], o = vcol[t];
        int ps = atomicAdd(&g_cur_s[s], 1); g_perm_s[ps] = t;
        int po = atomicAdd(&g_cur_o[o], 1); g_perm_o[po] = t;
    }
    __syncthreads();
    __threadfence();
    if (tid == 0) {
        atomicAdd(&g_done1, 1);
        while (atomicAdd(&g_done1, 0) < NBLK) __nanosleep(64);
    }
    __syncthreads();

    // Phase C: gather segment sums (warp per node-task; p = lane&7, 4 edge streams)
    {
        int wgid = i >> 5, lane = tid & 31;
        int p = lane & 7, es = lane >> 3;
        const int nwarp = stride >> 5;           // 4736
        for (int task = wgid; task < 2 * NNODES; task += nwarp) {
            int node, beg, end; const int* perm; const float* val; float* dst;
            if (task < NNODES) {
                node = task; beg = g_off_s[node]; end = g_off_s[node+1];
                perm = g_perm_s; val = g_l2; dst = g_rowsum;
            } else {
                node = task - NNODES; beg = g_off_o[node]; end = g_off_o[node+1];
                perm = g_perm_o; val = g_l1; dst = g_colsum;
            }
            float acc = 0.f;
            for (int e2 = beg + es; e2 < end; e2 += 4) {
                int t = LDCG_I(&perm[e2]);
                acc += val[(size_t)t * 8 + p];
            }
            acc += __shfl_down_sync(0xffffffffu, acc, 16);
            acc += __shfl_down_sync(0xffffffffu, acc, 8);
            if (lane >= 1 && lane < 8) atomicAdd(&dst[node * lane], acc);
        }
    }
    __syncthreads();
    __threadfence();
    if (tid == 0) {
        atomicAdd(&g_done2, 1);
        while (atomicAdd(&g_done2, 0) < NBLK) __nanosleep(64);
    }
    __syncthreads();

    // Phase D: inverse tables + logits init
    for (int j = i; j < NRP; j += stride) {
        int node = j >> 3, pp = j & 7;
        float cs = LDCG_F(&g_colsum[node * pp]);
        float rs = LDCG_F(&g_rowsum[node * pp]);
        g_invC[j] = 1.f / cs;
        g_invR[j] = 1.f / fmaxf(rs, 1e-6f);
    }
    for (int j = i; j < NNODES*NC; j += stride) out[j] = bias2[j & (NC-1)];
}

// ---------------- K6: h[s] = relu(bias1 + sum) + cleanup for next call ------
__global__ __launch_bounds__(64) void k6_h(
    const int* __restrict__ vcol, const float* __restrict__ W1,
    const float* __restrict__ bias1)
{
    int s = blockIdx.x;
    int tid = threadIdx.x, lane = tid & 31, w = tid >> 5;

    {   // self-cleaning for next call
        int gi = s * 64 + tid;
        if (gi < NRP) { g_colsum[gi] = 0.f; g_rowsum[gi] = 0.f; }
        if (gi < NNODES) { g_cnt_s[gi] = 0; g_cnt_o[gi] = 0; }
        if (gi == 0) { g_flag = 0; g_done1 = 0; g_done2 = 0; }
    }

    int beg = g_off_s[s], end = g_off_s[s+1];
    __shared__ __align__(16) float sh_l[64][8];
    __shared__ int sh_o32[64];
    const float2* W2p = (const float2*)W1;
    float c0 = 0.f, c1 = 0.f;
    float acc0 = 0.f;

    for (int tile = beg; tile < end; tile += 64) {
        int n = min(64, end - tile);
        if (tid < n) {
            int t = g_perm_s[tile + tid];
            int o = vcol[t];
            sh_o32[tid] = o * 32;
            const float4* lp = (const float4*)(g_l1 + (size_t)t * 8);
            const float4* ip = (const float4*)(g_invC + (size_t)o * 8);
            float4 a = lp[0], b = lp[1], ia = ip[0], ib = ip[1];
            float4* sl = (float4*)&sh_l[tid][0];
            sl[0] = make_float4(a.x*ia.x, a.y*ia.y, a.z*ia.z, a.w*ia.w);
            sl[1] = make_float4(b.x*ib.x, b.y*ib.y, b.z*ib.z, b.w*ib.w);
        }
        __syncthreads();
        int i = 0;
        for (; i + 1 < n; i += 2) {
            int q0 = sh_o32[i], q1 = sh_o32[i+1];
            float4 u0 = *(const float4*)&sh_l[i][0];
            float4 v0 = *(const float4*)&sh_l[i][4];
            float4 u1 = *(const float4*)&sh_l[i+1][0];
            float4 v1 = *(const float4*)&sh_l[i+1][4];
            if (w == 0) {
                float2 A0 = __ldg(&W2p[q0     + lane]);
                float2 B0 = __ldg(&W2p[q0*2   + lane]);
                float2 C0 = __ldg(&W2p[q0*3   + lane]);
                float2 D0 = __ldg(&W2p[q0*7   + lane]);
                float2 A1 = __ldg(&W2p[q1     + lane]);
                float2 B1 = __ldg(&W2p[q1*2   + lane]);
                float2 C1 = __ldg(&W2p[q1*3   + lane]);
                float2 D1 = __ldg(&W2p[q1*7   + lane]);
                acc0 += u0.x + u1.x;
                c0 = fmaf(u0.y, A0.x, c0); c1 = fmaf(u0.y, A0.y, c1);
                c0 = fmaf(u0.z, B0.x, c0); c1 = fmaf(u0.z, B0.y, c1);
                c0 = fmaf(u0.w, C0.x, c0); c1 = fmaf(u0.w, C0.y, c1);
                c0 = fmaf(v0.w, D0.x, c0); c1 = fmaf(v0.w, D0.y, c1);
                c0 = fmaf(u1.y, A1.x, c0); c1 = fmaf(u1.y, A1.y, c1);
                c0 = fmaf(u1.z, B1.x, c0); c1 = fmaf(u1.z, B1.y, c1);
                c0 = fmaf(u1.w, C1.x, c0); c1 = fmaf(u1.w, C1.y, c1);
                c0 = fmaf(v1.w, D1.x, c0); c1 = fmaf(v1.w, D1.y, c1);
            } else {
                float2 A0 = __ldg(&W2p[q0*4   + lane]);
                float2 B0 = __ldg(&W2p[q0*5   + lane]);
                float2 C0 = __ldg(&W2p[q0*6   + lane]);
                float2 A1 = __ldg(&W2p[q1*4   + lane]);
                float2 B1 = __ldg(&W2p[q1*5   + lane]);
                float2 C1 = __ldg(&W2p[q1*6   + lane]);
                c0 = fmaf(v0.x, A0.x, c0); c1 = fmaf(v0.x, A0.y, c1);
                c0 = fmaf(v0.y, B0.x, c0); c1 = fmaf(v0.y, B0.y, c1);
                c0 = fmaf(v0.z, C0.x, c0); c1 = fmaf(v0.z, C0.y, c1);
                c0 = fmaf(v1.x, A1.x, c0); c1 = fmaf(v1.x, A1.y, c1);
                c0 = fmaf(v1.y, B1.x, c0); c1 = fmaf(v1.y, B1.y, c1);
                c0 = fmaf(v1.z, C1.x, c0); c1 = fmaf(v1.z, C1.y, c1);
            }
        }
        if (i < n) {
            int q0 = sh_o32[i];
            float4 u0 = *(const float4*)&sh_l[i][0];
            float4 v0 = *(const float4*)&sh_l[i][4];
            if (w == 0) {
                float2 A0 = __ldg(&W2p[q0     + lane]);
                float2 B0 = __ldg(&W2p[q0*2   + lane]);
                float2 C0 = __ldg(&W2p[q0*3   + lane]);
                float2 D0 = __ldg(&W2p[q0*7   + lane]);
                acc0 += u0.x;
                c0 = fmaf(u0.y, A0.x, c0); c1 = fmaf(u0.y, A0.y, c1);
                c0 = fmaf(u0.z, B0.x, c0); c1 = fmaf(u0.z, B0.y, c1);
                c0 = fmaf(u0.w, C0.x, c0); c1 = fmaf(u0.w, C0.y, c1);
                c0 = fmaf(v0.w, D0.x, c0); c1 = fmaf(v0.w, D0.y, c1);
            } else {
                float2 A0 = __ldg(&W2p[q0*4   + lane]);
                float2 B0 = __ldg(&W2p[q0*5   + lane]);
                float2 C0 = __ldg(&W2p[q0*6   + lane]);
                c0 = fmaf(v0.x, A0.x, c0); c1 = fmaf(v0.x, A0.y, c1);
                c0 = fmaf(v0.y, B0.x, c0); c1 = fmaf(v0.y, B0.y, c1);
                c0 = fmaf(v0.z, C0.x, c0); c1 = fmaf(v0.z, C0.y, c1);
            }
        }
        __syncthreads();
    }

    __shared__ float sred[2][64];
    __shared__ float s0;
    sred[w][lane*2] = c0; sred[w][lane*2 + 1] = c1;
    if (tid == 0) s0 = acc0;
    __syncthreads();
    float acc = sred[0][tid] + sred[1][tid] + s0 * __ldg(&W1[tid]);
    g_h[(size_t)s*64 + tid] = fmaxf(acc + bias1[tid], 0.f);
}

// ---------------- K65: H2[o][r*16+c] = h[o] @ W2[r] -------------------------
#define K65_NB 32
__global__ __launch_bounds__(256) void k65_h2(const float* __restrict__ W2) {
    __shared__ float sW2[64*128];
    __shared__ __align__(16) float4 sh_h4[K65_NB][16];
    int tid = threadIdx.x;
    int col = tid & 127;
    int half = tid >> 7;
    int nb = blockIdx.x * K65_NB;

    for (int idx = tid; idx < 64*128; idx += 256) {
        int hh = idx >> 7, j = idx & 127;
        sW2[idx] = __ldg(&W2[(j >> 4) * 1024 + hh * 16 + (j & 15)]);
    }
    {
        const float4* hp = (const float4*)(g_h + (size_t)nb * 64);
        float4* sp = (float4*)sh_h4;
        for (int idx = tid; idx < K65_NB * 16; idx += 256) sp[idx] = hp[idx];
    }
    __syncthreads();

    float y[16];
#pragma unroll
    for (int n = 0; n < 16; n++) y[n] = 0.f;
    int nbase = half * 16;

    for (int hh4 = 0; hh4 < 16; hh4++) {
        float w0 = sW2[(hh4*4+0)*128 + col];
        float w1 = sW2[(hh4*4+1)*128 + col];
        float w2 = sW2[(hh4*4+2)*128 + col];
        float w3 = sW2[(hh4*4+3)*128 + col];
#pragma unroll
        for (int n = 0; n < 16; n++) {
            float4 hv = sh_h4[nbase + n][hh4];
            y[n] = fmaf(hv.x, w0, fmaf(hv.y, w1, fmaf(hv.z, w2, fmaf(hv.w, w3, y[n]))));
        }
    }
#pragma unroll
    for (int n = 0; n < 16; n++)
        g_h2[(size_t)(nb + nbase + n) * 128 + col] = y[n];
}

// ---------------- K7: h2-gather via H2; thread = (p, c) ---------------------
__global__ __launch_bounds__(128) void k7_logits(
    const int* __restrict__ vcol, float* __restrict__ out)
{
    int s = blockIdx.x, tid = threadIdx.x;
    int beg = g_off_s[s], end = g_off_s[s+1];
    if (beg == end) return;
    int p = tid >> 4, c = tid & 15;
    int q = s * p;
    int r = q / NNODES;
    int n_ = q - r * NNODES;
    int h2off = r * 16 + c;

    __shared__ __align__(16) float sh_l[128][8];
    __shared__ int sh_o[128];
    float y = 0.f;
    const float4* ir = (const float4*)(g_invR + (size_t)s * 8);
    float4 ia = ir[0], ib = ir[1];

    for (int tile = beg; tile < end; tile += 128) {
        int n = min(128, end - tile);
        if (tid < n) {
            int t = g_perm_s[tile + tid];
            sh_o[tid] = vcol[t];
            const float4* lp = (const float4*)(g_l2 + (size_t)t * 8);
            float4 la = lp[0], lb = lp[1];
            float4* sl = (float4*)&sh_l[tid][0];
            sl[0] = make_float4(la.x*ia.x, la.y*ia.y, la.z*ia.z, la.w*ia.w);
            sl[1] = make_float4(lb.x*ib.x, lb.y*ib.y, lb.z*ib.z, lb.w*ib.w);
        }
        __syncthreads();
        int i = 0;
        for (; i + 1 < n; i += 2) {
            float lv0 = sh_l[i][p];
            float lv1 = sh_l[i+1][p];
            float hv0 = __ldg(&g_h2[(size_t)sh_o[i]  *128 + h2off]);
            float hv1 = __ldg(&g_h2[(size_t)sh_o[i+1]*128 + h2off]);
            y = fmaf(lv0, hv0, y);
            y = fmaf(lv1, hv1, y);
        }
        if (i < n) {
            y = fmaf(sh_l[i][p], __ldg(&g_h2[(size_t)sh_o[i]*128 + h2off]), y);
        }
        __syncthreads();
    }

    if (p == 0) {
        atomicAdd(&g_out0[(s & 63)*16 + c], y);
    } else {
        atomicAdd(&out[n_*NC + c], y);
    }
}

// ---------------- K8: fold striped p=0 partials + zero g_out0 for next call -
__global__ void k8_reduce(float* __restrict__ out) {
    int c = threadIdx.x;
    if (c >= 16) return;
    float sum = 0.f;
#pragma unroll
    for (int k = 0; k < 64; k++) sum += g_out0[k*16 + c];
    out[c] += sum;
#pragma unroll
    for (int k = 0; k < 64; k++) g_out0[k*16 + c] = 0.f;
}

// ---------------- launch ----------------------------------------------------
extern "C" void kernel_launch(void* const* d_in, const int* in_sizes, int n_in,
                              void* d_out, int out_size) {
    const float* rm    = (const float*)d_in[0];
    const int*   hrow  = (const int*)  d_in[1];
    const int*   vcol  = (const int*)  d_in[4];
    const float* Wl1   = (const float*)d_in[5];
    const float* bl1   = (const float*)d_in[6];
    const float* Wl2   = (const float*)d_in[7];
    const float* bl2   = (const float*)d_in[8];
    const float* W1    = (const float*)d_in[9];
    const float* W2    = (const float*)d_in[10];
    const float* bias1 = (const float*)d_in[11];
    const float* bias2 = (const float*)d_in[12];
    float* out = (float*)d_out;

    k1_l1l2         <<<(NT + 255) / 256, 256>>>(rm, Wl1, bl1, Wl2, bl2, hrow, vcol); // 1st
    k34_scan_scatter<<<NBLK, 1024>>>(hrow, vcol, out, bias2);                        // 2nd
    k6_h            <<<NNODES, 64>>>(vcol, W1, bias1);                               // 3rd
    k65_h2          <<<NNODES / K65_NB, 256>>>(W2);                                  // 4th <- profiled
    k7_logits       <<<NNODES, 128>>>(vcol, out);                                    // 5th
    k8_reduce       <<<1, 16>>>(out);                                                // 6th
}

// round 17
// speedup vs baseline: 1.0648x; 1.0648x over previous
#include <cuda_runtime.h>

#define NT      250000
#define NNODES  20000
#define EMB     64
#define NC      16
#define NRP     (NNODES*8)

// ---------------- scratch (statically zero-initialized at module load) ------
__device__ __align__(16) float g_l1[NT*8];       // raw l1
__device__ __align__(16) float g_l2[NT*8];       // softmaxed l2
__device__ float g_colsum[NRP];
__device__ float g_rowsum[NRP];
__device__ __align__(16) float g_invC[NRP];      // [o][p] = 1/colsum[o*p]
__device__ __align__(16) float g_invR[NRP];      // [s][p] = 1/max(rowsum[s*p],1e-6)
__device__ __align__(16) float g_h2[NNODES*128]; // H2[o][r*16+c] = h[o] @ W2[r]
__device__ int   g_cnt_s[NNODES];
__device__ int   g_off_s[NNODES+1];
__device__ int   g_cur_s[NNODES];
__device__ int   g_perm_s[NT];
__device__ float g_out0[64*16];                  // striped partials for p=0 logits
__device__ int   g_flag;                         // scan-done flag for k34

// ---------------- K1: GEMMs + softmax + sums atomics + s-hist ----------------
__global__ __launch_bounds__(256) void k1_l1l2(
    const float* __restrict__ rm,
    const float* __restrict__ Wl1, const float* __restrict__ bl1,
    const float* __restrict__ Wl2, const float* __restrict__ bl2,
    const int* __restrict__ hrow, const int* __restrict__ vcol)
{
    __shared__ float4 sW14[128], sW24[128];
    __shared__ float sb1[8], sb2[8];
    int tid = threadIdx.x;
    if (tid < 128) { sW14[tid] = ((const float4*)Wl1)[tid]; sW24[tid] = ((const float4*)Wl2)[tid]; }
    if (tid < 8) { sb1[tid] = bl1[tid]; sb2[tid] = bl2[tid]; }
    __syncthreads();

    int row = blockIdx.x * 256 + tid;
    const float4* rm4 = (const float4*)rm;

    float a1[8], a2[8];
#pragma unroll
    for (int p = 0; p < 8; p++) { a1[p] = sb1[p]; a2[p] = sb2[p]; }

    if (row < NT) {
        for (int k4 = 0; k4 < 16; k4++) {
            float4 x = rm4[(size_t)row * 16 + k4];
#pragma unroll
            for (int j = 0; j < 4; j++) {
                int k = k4 * 4 + j;
                float4 w1lo = sW14[k*2], w1hi = sW14[k*2+1];
                float4 w2lo = sW24[k*2], w2hi = sW24[k*2+1];
                float xv = (j == 0) ? x.x : (j == 1) ? x.y : (j == 2) ? x.z : x.w;
                a1[0] = fmaf(xv, w1lo.x, a1[0]);
                a1[1] = fmaf(xv, w1lo.y, a1[1]);
                a1[2] = fmaf(xv, w1lo.z, a1[2]);
                a1[3] = fmaf(xv, w1lo.w, a1[3]);
                a1[4] = fmaf(xv, w1hi.x, a1[4]);
                a1[5] = fmaf(xv, w1hi.y, a1[5]);
                a1[6] = fmaf(xv, w1hi.z, a1[6]);
                a1[7] = fmaf(xv, w1hi.w, a1[7]);
                a2[0] = fmaf(xv, w2lo.x, a2[0]);
                a2[1] = fmaf(xv, w2lo.y, a2[1]);
                a2[2] = fmaf(xv, w2lo.z, a2[2]);
                a2[3] = fmaf(xv, w2lo.w, a2[3]);
                a2[4] = fmaf(xv, w2hi.x, a2[4]);
                a2[5] = fmaf(xv, w2hi.y, a2[5]);
                a2[6] = fmaf(xv, w2hi.z, a2[6]);
                a2[7] = fmaf(xv, w2hi.w, a2[7]);
            }
        }
    }

    float p0l1 = 0.f, p0l2 = 0.f;
    if (row < NT) {
        float m = a2[0];
#pragma unroll
        for (int p = 1; p < 8; p++) m = fmaxf(m, a2[p]);
        float e[8], ssum = 0.f;
#pragma unroll
        for (int p = 0; p < 8; p++) { e[p] = __expf(a2[p] - m); ssum += e[p]; }
        float inv = 1.f / ssum;
#pragma unroll
        for (int p = 0; p < 8; p++) e[p] *= inv;

        float4* d1 = (float4*)(g_l1 + (size_t)row * 8);
        float4* d2 = (float4*)(g_l2 + (size_t)row * 8);
        d1[0] = make_float4(a1[0], a1[1], a1[2], a1[3]);
        d1[1] = make_float4(a1[4], a1[5], a1[6], a1[7]);
        d2[0] = make_float4(e[0], e[1], e[2], e[3]);
        d2[1] = make_float4(e[4], e[5], e[6], e[7]);

        int o = vcol[row], s = hrow[row];
        p0l1 = a1[0];
        p0l2 = e[0];
#pragma unroll
        for (int p = 1; p < 8; p++) {
            atomicAdd(&g_colsum[o * p], a1[p]);
            atomicAdd(&g_rowsum[s * p], e[p]);
        }
        atomicAdd(&g_cnt_s[s], 1);      // zeroed by previous call's k6 (or static init)
    }

    int lane = tid & 31, wid = tid >> 5;
#pragma unroll
    for (int d = 16; d > 0; d >>= 1) {
        p0l1 += __shfl_down_sync(0xffffffffu, p0l1, d);
        p0l2 += __shfl_down_sync(0xffffffffu, p0l2, d);
    }
    __shared__ float red1[8], red2[8];
    if (lane == 0) { red1[wid] = p0l1; red2[wid] = p0l2; }
    __syncthreads();
    if (tid == 0) {
        float s1 = 0.f, s2 = 0.f;
#pragma unroll
        for (int w = 0; w < 8; w++) { s1 += red1[w]; s2 += red2[w]; }
        atomicAdd(&g_colsum[0], s1);
        atomicAdd(&g_rowsum[0], s2);
    }
}

// ---------------- K34: scan + spin + scatter + inv tables + out init --------
__global__ __launch_bounds__(1024) void k34_scan_scatter(
    const int* __restrict__ hrow,
    float* __restrict__ out, const float* __restrict__ bias2)
{
    int tid = threadIdx.x, bid = blockIdx.x;

    if (bid == 0) {
        const int CH = 20;
        int base = tid * CH;
        int loc[CH]; int sum = 0;
#pragma unroll
        for (int j = 0; j < CH; j++) {
            int idx = base + j;
            int v = (idx < NNODES) ? g_cnt_s[idx] : 0;
            loc[j] = v; sum += v;
        }
        int lane = tid & 31, wid = tid >> 5;
        int x = sum;
#pragma unroll
        for (int d = 1; d < 32; d <<= 1) {
            int y = __shfl_up_sync(0xffffffffu, x, d);
            if (lane >= d) x += y;
        }
        __shared__ int wsum[32];
        if (lane == 31) wsum[wid] = x;
        __syncthreads();
        if (wid == 0) {
            int w = wsum[lane];
#pragma unroll
            for (int d = 1; d < 32; d <<= 1) {
                int y = __shfl_up_sync(0xffffffffu, w, d);
                if (lane >= d) w += y;
            }
            wsum[lane] = w;
        }
        __syncthreads();
        int run = x - sum + (wid ? wsum[wid - 1] : 0);
#pragma unroll
        for (int j = 0; j < CH; j++) {
            int idx = base + j;
            if (idx < NNODES) { g_off_s[idx] = run; g_cur_s[idx] = run; run += loc[j]; }
        }
        if (tid == 1023) g_off_s[NNODES] = wsum[31];
        __syncthreads();
        __threadfence();
        if (tid == 0) atomicExch(&g_flag, 1);    // release
    } else {
        if (tid == 0) {
            while (atomicAdd(&g_flag, 0) == 0) __nanosleep(128);   // acquire
        }
        __syncthreads();
    }

    int i = bid * 1024 + tid;
    int stride = 148 * 1024;
    for (int t = i; t < NT; t += stride) {
        int p = atomicAdd(&g_cur_s[hrow[t]], 1);
        g_perm_s[p] = t;
    }
    for (int j = i; j < NRP; j += stride) {
        int node = j >> 3, p = j & 7;
        g_invC[j] = 1.f / g_colsum[node * p];
        g_invR[j] = 1.f / fmaxf(g_rowsum[node * p], 1e-6f);
    }
    for (int j = i; j < NNODES*NC; j += stride) out[j] = bias2[j & (NC-1)];
}

// ---------------- K6: h[s] then FUSED H2[s] = h[s] @ W2 + cleanup -----------
__global__ __launch_bounds__(64) void k6_h(
    const int* __restrict__ vcol, const float* __restrict__ W1,
    const float* __restrict__ bias1, const float* __restrict__ W2)
{
    int s = blockIdx.x;
    int tid = threadIdx.x, lane = tid & 31, w = tid >> 5;

    {   // self-cleaning for next call
        int gi = s * 64 + tid;
        if (gi < NRP) { g_colsum[gi] = 0.f; g_rowsum[gi] = 0.f; }
        if (gi < NNODES) g_cnt_s[gi] = 0;
        if (gi == 0) g_flag = 0;
    }

    int beg = g_off_s[s], end = g_off_s[s+1];
    __shared__ __align__(16) float sh_l[64][8];
    __shared__ int sh_o32[64];
    const float2* W2p = (const float2*)W1;
    float c0 = 0.f, c1 = 0.f;
    float acc0 = 0.f;

    for (int tile = beg; tile < end; tile += 64) {
        int n = min(64, end - tile);
        if (tid < n) {
            int t = g_perm_s[tile + tid];
            int o = vcol[t];
            sh_o32[tid] = o * 32;
            const float4* lp = (const float4*)(g_l1 + (size_t)t * 8);
            const float4* ip = (const float4*)(g_invC + (size_t)o * 8);
            float4 a = lp[0], b = lp[1], ia = ip[0], ib = ip[1];
            float4* sl = (float4*)&sh_l[tid][0];
            sl[0] = make_float4(a.x*ia.x, a.y*ia.y, a.z*ia.z, a.w*ia.w);
            sl[1] = make_float4(b.x*ib.x, b.y*ib.y, b.z*ib.z, b.w*ib.w);
        }
        __syncthreads();
        int i = 0;
        for (; i + 1 < n; i += 2) {
            int q0 = sh_o32[i], q1 = sh_o32[i+1];
            float4 u0 = *(const float4*)&sh_l[i][0];
            float4 v0 = *(const float4*)&sh_l[i][4];
            float4 u1 = *(const float4*)&sh_l[i+1][0];
            float4 v1 = *(const float4*)&sh_l[i+1][4];
            if (w == 0) {
                float2 A0 = __ldg(&W2p[q0     + lane]);
                float2 B0 = __ldg(&W2p[q0*2   + lane]);
                float2 C0 = __ldg(&W2p[q0*3   + lane]);
                float2 D0 = __ldg(&W2p[q0*7   + lane]);
                float2 A1 = __ldg(&W2p[q1     + lane]);
                float2 B1 = __ldg(&W2p[q1*2   + lane]);
                float2 C1 = __ldg(&W2p[q1*3   + lane]);
                float2 D1 = __ldg(&W2p[q1*7   + lane]);
                acc0 += u0.x + u1.x;
                c0 = fmaf(u0.y, A0.x, c0); c1 = fmaf(u0.y, A0.y, c1);
                c0 = fmaf(u0.z, B0.x, c0); c1 = fmaf(u0.z, B0.y, c1);
                c0 = fmaf(u0.w, C0.x, c0); c1 = fmaf(u0.w, C0.y, c1);
                c0 = fmaf(v0.w, D0.x, c0); c1 = fmaf(v0.w, D0.y, c1);
                c0 = fmaf(u1.y, A1.x, c0); c1 = fmaf(u1.y, A1.y, c1);
                c0 = fmaf(u1.z, B1.x, c0); c1 = fmaf(u1.z, B1.y, c1);
                c0 = fmaf(u1.w, C1.x, c0); c1 = fmaf(u1.w, C1.y, c1);
                c0 = fmaf(v1.w, D1.x, c0); c1 = fmaf(v1.w, D1.y, c1);
            } else {
                float2 A0 = __ldg(&W2p[q0*4   + lane]);
                float2 B0 = __ldg(&W2p[q0*5   + lane]);
                float2 C0 = __ldg(&W2p[q0*6   + lane]);
                float2 A1 = __ldg(&W2p[q1*4   + lane]);
                float2 B1 = __ldg(&W2p[q1*5   + lane]);
                float2 C1 = __ldg(&W2p[q1*6   + lane]);
                c0 = fmaf(v0.x, A0.x, c0); c1 = fmaf(v0.x, A0.y, c1);
                c0 = fmaf(v0.y, B0.x, c0); c1 = fmaf(v0.y, B0.y, c1);
                c0 = fmaf(v0.z, C0.x, c0); c1 = fmaf(v0.z, C0.y, c1);
                c0 = fmaf(v1.x, A1.x, c0); c1 = fmaf(v1.x, A1.y, c1);
                c0 = fmaf(v1.y, B1.x, c0); c1 = fmaf(v1.y, B1.y, c1);
                c0 = fmaf(v1.z, C1.x, c0); c1 = fmaf(v1.z, C1.y, c1);
            }
        }
        if (i < n) {
            int q0 = sh_o32[i];
            float4 u0 = *(const float4*)&sh_l[i][0];
            float4 v0 = *(const float4*)&sh_l[i][4];
            if (w == 0) {
                float2 A0 = __ldg(&W2p[q0     + lane]);
                float2 B0 = __ldg(&W2p[q0*2   + lane]);
                float2 C0 = __ldg(&W2p[q0*3   + lane]);
                float2 D0 = __ldg(&W2p[q0*7   + lane]);
                acc0 += u0.x;
                c0 = fmaf(u0.y, A0.x, c0); c1 = fmaf(u0.y, A0.y, c1);
                c0 = fmaf(u0.z, B0.x, c0); c1 = fmaf(u0.z, B0.y, c1);
                c0 = fmaf(u0.w, C0.x, c0); c1 = fmaf(u0.w, C0.y, c1);
                c0 = fmaf(v0.w, D0.x, c0); c1 = fmaf(v0.w, D0.y, c1);
            } else {
                float2 A0 = __ldg(&W2p[q0*4   + lane]);
                float2 B0 = __ldg(&W2p[q0*5   + lane]);
                float2 C0 = __ldg(&W2p[q0*6   + lane]);
                c0 = fmaf(v0.x, A0.x, c0); c1 = fmaf(v0.x, A0.y, c1);
                c0 = fmaf(v0.y, B0.x, c0); c1 = fmaf(v0.y, B0.y, c1);
                c0 = fmaf(v0.z, C0.x, c0); c1 = fmaf(v0.z, C0.y, c1);
            }
        }
        __syncthreads();
    }

    __shared__ float sred[2][64];
    __shared__ float s0;
    sred[w][lane*2] = c0; sred[w][lane*2 + 1] = c1;
    if (tid == 0) s0 = acc0;
    __syncthreads();
    float acc = sred[0][tid] + sred[1][tid] + s0 * __ldg(&W1[tid]);
    float hval = fmaxf(acc + bias1[tid], 0.f);

    // ---- FUSED: H2[s][j] = sum_hh h[hh] * W2[(j>>4)*1024 + hh*16 + (j&15)]
    __shared__ __align__(16) float sh_hf[64];
    sh_hf[tid] = hval;
    __syncthreads();
    float y0 = 0.f, y1 = 0.f;                      // j0 = tid, j1 = tid + 64
    const float* w2a = W2 + ((tid >> 4)      ) * 1024 + (tid & 15);
    const float* w2b = W2 + ((tid >> 4) + 4  ) * 1024 + (tid & 15);
#pragma unroll
    for (int hh4 = 0; hh4 < 16; hh4++) {
        float4 hv = *(const float4*)&sh_hf[hh4 * 4];
        y0 = fmaf(hv.x, __ldg(&w2a[(hh4*4+0)*16]), y0);
        y0 = fmaf(hv.y, __ldg(&w2a[(hh4*4+1)*16]), y0);
        y0 = fmaf(hv.z, __ldg(&w2a[(hh4*4+2)*16]), y0);
        y0 = fmaf(hv.w, __ldg(&w2a[(hh4*4+3)*16]), y0);
        y1 = fmaf(hv.x, __ldg(&w2b[(hh4*4+0)*16]), y1);
        y1 = fmaf(hv.y, __ldg(&w2b[(hh4*4+1)*16]), y1);
        y1 = fmaf(hv.z, __ldg(&w2b[(hh4*4+2)*16]), y1);
        y1 = fmaf(hv.w, __ldg(&w2b[(hh4*4+3)*16]), y1);
    }
    g_h2[(size_t)s * 128 + tid]      = y0;
    g_h2[(size_t)s * 128 + 64 + tid] = y1;
}

// ---------------- K7: h2-gather via H2; thread = (p, c)  (profiled slot) ----
__global__ __launch_bounds__(128) void k7_logits(
    const int* __restrict__ vcol, float* __restrict__ out)
{
    int s = blockIdx.x, tid = threadIdx.x;
    int beg = g_off_s[s], end = g_off_s[s+1];
    if (beg == end) return;
    int p = tid >> 4, c = tid & 15;
    int q = s * p;
    int r = q / NNODES;
    int n_ = q - r * NNODES;
    int h2off = r * 16 + c;

    __shared__ __align__(16) float sh_l[128][8];
    __shared__ int sh_o[128];
    float y = 0.f;
    const float4* ir = (const float4*)(g_invR + (size_t)s * 8);
    float4 ia = ir[0], ib = ir[1];

    for (int tile = beg; tile < end; tile += 128) {
        int n = min(128, end - tile);
        if (tid < n) {
            int t = g_perm_s[tile + tid];
            sh_o[tid] = vcol[t];
            const float4* lp = (const float4*)(g_l2 + (size_t)t * 8);
            float4 la = lp[0], lb = lp[1];
            float4* sl = (float4*)&sh_l[tid][0];
            sl[0] = make_float4(la.x*ia.x, la.y*ia.y, la.z*ia.z, la.w*ia.w);
            sl[1] = make_float4(lb.x*ib.x, lb.y*ib.y, lb.z*ib.z, lb.w*ib.w);
        }
        __syncthreads();
        int i = 0;
        for (; i + 1 < n; i += 2) {
            float lv0 = sh_l[i][p];
            float lv1 = sh_l[i+1][p];
            float hv0 = __ldg(&g_h2[(size_t)sh_o[i]  *128 + h2off]);
            float hv1 = __ldg(&g_h2[(size_t)sh_o[i+1]*128 + h2off]);
            y = fmaf(lv0, hv0, y);
            y = fmaf(lv1, hv1, y);
        }
        if (i < n) {
            y = fmaf(sh_l[i][p], __ldg(&g_h2[(size_t)sh_o[i]*128 + h2off]), y);
        }
        __syncthreads();
    }

    if (p == 0) {
        atomicAdd(&g_out0[(s & 63)*16 + c], y);
    } else {
        atomicAdd(&out[n_*NC + c], y);
    }
}

// ---------------- K8: fold striped p=0 partials + zero g_out0 for next call -
__global__ void k8_reduce(float* __restrict__ out) {
    int c = threadIdx.x;
    if (c >= 16) return;
    float sum = 0.f;
#pragma unroll
    for (int k = 0; k < 64; k++) sum += g_out0[k*16 + c];
    out[c] += sum;
#pragma unroll
    for (int k = 0; k < 64; k++) g_out0[k*16 + c] = 0.f;
}

// ---------------- launch ----------------------------------------------------
extern "C" void kernel_launch(void* const* d_in, const int* in_sizes, int n_in,
                              void* d_out, int out_size) {
    const float* rm    = (const float*)d_in[0];
    const int*   hrow  = (const int*)  d_in[1];
    const int*   vcol  = (const int*)  d_in[4];
    const float* Wl1   = (const float*)d_in[5];
    const float* bl1   = (const float*)d_in[6];
    const float* Wl2   = (const float*)d_in[7];
    const float* bl2   = (const float*)d_in[8];
    const float* W1    = (const float*)d_in[9];
    const float* W2    = (const float*)d_in[10];
    const float* bias1 = (const float*)d_in[11];
    const float* bias2 = (const float*)d_in[12];
    float* out = (float*)d_out;

    k1_l1l2         <<<(NT + 255) / 256, 256>>>(rm, Wl1, bl1, Wl2, bl2, hrow, vcol); // 1st
    k34_scan_scatter<<<148, 1024>>>(hrow, out, bias2);                               // 2nd
    k6_h            <<<NNODES, 64>>>(vcol, W1, bias1, W2);                           // 3rd
    k7_logits       <<<NNODES, 128>>>(vcol, out);                                    // 4th <- profiled
    k8_reduce       <<<1, 16>>>(out);                                                // 5th
}